// round 12
// baseline (speedup 1.0000x reference)
#include <cuda_runtime.h>

#define NINST 100
#define HW 819200              // 640*1280
#define TPB 256
#define PXT 4                  // pixels per thread (float4)
#define NTILES 1600            // 800 reader + 800 writer tiles (parity-interleaved)
#define GRID 740               // 148 SMs x 5 resident blocks = single persistent wave
#define WCHUNK (NINST * HW / 800)    // 102400 floats per writer tile
#define UCH 8                  // planes per software-pipeline chunk

// ---------------- static device state (no allocations) ----------------
__device__ unsigned g_tile;                            // work-stealing cursor
__device__ unsigned g_rawcnt;                          // epilogue resets all of these
__device__ unsigned g_npairs;
__device__ unsigned g_done;
__device__ int      g_hist[NINST];                     // per-rank candidate counts
__device__ unsigned g_aff[4];                          // 128-bit affected-rank mask
__device__ __align__(16) unsigned long long g_rec[HW]; // packed (p | nA<<20 | nB<<27)
__device__ __align__(16) unsigned g_pair[HW];          // packed (nA | nB<<8)

// ---------------- single fused persistent kernel ----------------
// 740 persistent blocks steal tiles 0..1599. Odd tiles: pure STG.128 zero-fill
// of the output planes. Even tiles: pure-read streaming max + unshifted
// sum(exp) over the 100 planes in descending-confidence order; rare candidate
// emission (softmax >= 0.4 admits at most the per-pixel top-2) updates the
// global hist / same-class pair list INLINE, so the last-block epilogue only
// computes keep + runs one assignment scan.
__global__ void __launch_bounds__(TPB, 5) k_fused(const float* __restrict__ mask,
                                                  float* __restrict__ masks_out,
                                                  const float* __restrict__ cls_prob,
                                                  const int*   __restrict__ cls_idx,
                                                  float* keep_out, float* order_out) {
    __shared__ float v[NINST];
    __shared__ int sord[NINST];
    __shared__ int sci[NINST];
    __shared__ int skeep[NINST];
    __shared__ unsigned stile;
    __shared__ int slast;

    int t = threadIdx.x;

    // ---- block-local argsort: stable ascending rank, reversed ----
    if (t < NINST) v[t] = cls_prob[t];
    __syncthreads();
    if (t < NINST) {
        float x = v[t];
        int r = 0;
#pragma unroll 4
        for (int j = 0; j < NINST; j++)
            r += (v[j] < x) || (v[j] == x && j < t);
        sord[NINST - 1 - r] = t;
    }
    __syncthreads();
    if (t < NINST) sci[t] = cls_idx[sord[t]];          // class per rank
    if (blockIdx.x == 0 && t < NINST && order_out) order_out[t] = (float)sord[t];
    __syncthreads();

    // ---- persistent work-stealing loop over tiles ----
    for (;;) {
        if (t == 0) stile = atomicAdd(&g_tile, 1u);
        __syncthreads();
        unsigned tile = stile;
        __syncthreads();                       // stile reusable next iter
        if (tile >= NTILES) break;

        if (tile & 1u) {
            // ============== writer tile: pure zero-fill stream ==============
            const float4 z4 = make_float4(0.f, 0.f, 0.f, 0.f);
            float4* dst = reinterpret_cast<float4*>(
                masks_out + (size_t)(tile >> 1) * WCHUNK) + t;
#pragma unroll 8
            for (int i = 0; i < WCHUNK / (TPB * 4); i++) {
                __stcs(dst, z4);
                dst += TPB;
            }
        } else {
            // ============== reader tile: pure-read streaming reduce =========
            int p0 = (int)(tile >> 1) * (TPB * PXT) + t * PXT;

            float m1[PXT], s[PXT];
#pragma unroll
            for (int e = 0; e < PXT; e++) { m1[e] = __int_as_float(0xff800000); s[e] = 0.f; }

            float4 buf[UCH];
            for (int n0 = 0; n0 < 96; n0 += UCH) {
#pragma unroll
                for (int u = 0; u < UCH; u++)
                    buf[u] = __ldcs(reinterpret_cast<const float4*>(
                        mask + (size_t)sord[n0 + u] * HW + p0));
#pragma unroll
                for (int u = 0; u < UCH; u++) {
                    float vv[PXT] = { buf[u].x, buf[u].y, buf[u].z, buf[u].w };
#pragma unroll
                    for (int e = 0; e < PXT; e++) {
                        m1[e] = fmaxf(m1[e], vv[e]);
                        s[e] += __expf(vv[e]);
                    }
                }
            }
#pragma unroll
            for (int u = 0; u < 4; u++)
                buf[u] = __ldcs(reinterpret_cast<const float4*>(
                    mask + (size_t)sord[96 + u] * HW + p0));
#pragma unroll
            for (int u = 0; u < 4; u++) {
                float vv[PXT] = { buf[u].x, buf[u].y, buf[u].z, buf[u].w };
#pragma unroll
                for (int e = 0; e < PXT; e++) {
                    m1[e] = fmaxf(m1[e], vv[e]);
                    s[e] += __expf(vv[e]);
                }
            }

            // ---- rare candidate emission + inline hist/pair updates ----
#pragma unroll
            for (int e = 0; e < PXT; e++) {
                float thr = 0.4f * s[e];
                if (__expf(m1[e]) >= thr) {
                    const float* col = mask + p0 + e;
                    float b1 = __int_as_float(0xff800000), b2 = b1;
                    int j1 = 127, j2 = 127;
                    for (int n = 0; n < NINST; n++) {
                        float val = __ldg(col + (size_t)sord[n] * HW);
                        bool g1 = val > b1;
                        bool g2 = val > b2;
                        j2 = g1 ? j1 : (g2 ? n : j2);
                        b2 = g1 ? b1 : (g2 ? val : b2);
                        j1 = g1 ? n : j1;
                        b1 = g1 ? val : b1;
                    }
                    bool c2 = (j2 < NINST) && (__expf(b2) >= thr);
                    int a = j1, b = c2 ? j2 : 127;
                    if (c2 && b < a) { int tmp = a; a = b; b = tmp; } // nA earlier
                    unsigned pos = atomicAdd(&g_rawcnt, 1u);
                    g_rec[pos] = (unsigned long long)(unsigned)(p0 + e)
                               | ((unsigned long long)a << 20)
                               | ((unsigned long long)b << 27);
                    atomicAdd(&g_hist[a], 1);
                    if (c2) {
                        atomicAdd(&g_hist[b], 1);
                        if (sci[a] == sci[b]) {
                            unsigned pp = atomicAdd(&g_npairs, 1u);
                            g_pair[pp] = (unsigned)a | ((unsigned)b << 8);
                            atomicOr(&g_aff[b >> 5], 1u << (b & 31));
                        }
                    }
                }
            }
        }
    }

    // ---- last-block-done handoff ----
    __syncthreads();
    __threadfence();                       // publish records / hist / zeros
    if (t == 0) {
        unsigned old = atomicAdd(&g_done, 1u);
        slast = (old == (unsigned)(gridDim.x - 1)) ? 1 : 0;
    }
    __syncthreads();
    if (!slast) return;
    __threadfence();                       // acquire other blocks' state

    // ---- slim epilogue: keep + fixup + assignment ----
    // overlap(n) > 0 requires a same-class pair at the same pixel (doubly rare):
    //   default keep = 0 < hist < HW, exact unless n is the later partner nB of
    //   a same-class pair -> sequential fixup over the tiny pair list.
    //   assign(nA) iff keep[nA]; assign(nB) iff keep[nB] && !keep[nA]
    int myhist = 0;
    if (t < NINST) {
        myhist = g_hist[t];
        skeep[t] = (myhist > 0 && myhist < HW) ? 1 : 0;
    }
    unsigned aff0 = g_aff[0], aff1 = g_aff[1], aff2 = g_aff[2], aff3 = g_aff[3];
    unsigned cnt = g_rawcnt; if (cnt > HW) cnt = HW;
    unsigned np  = g_npairs; if (np > HW) np = HW;
    __syncthreads();

    if (t < 32 && (aff0 | aff1 | aff2 | aff3)) {
        for (int n = 0; n < NINST; n++) {
            unsigned af = (n < 32) ? aff0 : (n < 64) ? aff1 : (n < 96) ? aff2 : aff3;
            if (!((af >> (n & 31)) & 1u)) continue;
            if (!skeep[n]) continue;
            int ov = 0;
            for (unsigned i = t; i < np; i += 32) {
                unsigned pr = g_pair[i];
                if ((int)(pr >> 8) == n) ov += skeep[pr & 0xFFu];
            }
            ov = (int)__reduce_add_sync(0xffffffffu, (unsigned)ov);
            if (t == 0 && ((float)ov / fmaxf((float)g_hist[n], 1.0f)) > 0.03f)
                skeep[n] = 0;
            __syncwarp();
        }
    }
    __syncthreads();

    if (t < NINST && keep_out) keep_out[t] = skeep[t] ? 1.0f : 0.0f;

    for (unsigned i = t; i < cnt; i += TPB) {
        unsigned long long r = g_rec[i];
        unsigned p = (unsigned)(r & 0xFFFFFu);
        int nA = (int)(r >> 20) & 0x7F;
        int nB = (int)(r >> 27) & 0x7F;
        if (skeep[nA])
            masks_out[(size_t)nA * HW + p] = mask[(size_t)sord[nA] * HW + p];
        if (nB < NINST && skeep[nB] && !skeep[nA])
            masks_out[(size_t)nB * HW + p] = mask[(size_t)sord[nB] * HW + p];
    }

    // ---- replay reset ----
    __syncthreads();
    if (t < NINST) g_hist[t] = 0;
    if (t < 4) g_aff[t] = 0;
    if (t == 0) { g_rawcnt = 0; g_npairs = 0; g_done = 0; g_tile = 0; }
}

// ---------------- launch (single persistent kernel) ----------------
extern "C" void kernel_launch(void* const* d_in, const int* in_sizes, int n_in,
                              void* d_out, int out_size) {
    const float* cls_prob = (const float*)d_in[0];
    const float* mask     = (const float*)d_in[1];
    const int*   cls_idx  = (const int*)d_in[2];
    float* out = (float*)d_out;

    size_t nhw = (size_t)NINST * HW;
    float* keep_out  = out;
    float* masks_out = out + NINST;
    float* order_out = out + NINST + nhw;
    if ((size_t)out_size < nhw + 2 * NINST) {   // layout fallback: masks only
        keep_out = nullptr; order_out = nullptr; masks_out = out;
    }

    k_fused<<<GRID, TPB>>>(mask, masks_out, cls_prob, cls_idx,
                           keep_out, order_out);
}